// round 6
// baseline (speedup 1.0000x reference)
#include <cuda_runtime.h>
#include <math.h>

#define Nx   256
#define BN   2048      // 8*256

// ---------------- scratch ----------------
__device__ float g_A [BN*128];   // h @ Wm1[0:128]
__device__ float g_Bm[BN*128];   // h @ Wm1[128:256]
__device__ float g_P [BN*128];   // h @ Wu_top
__device__ float g_as[BN];
__device__ float g_bs[BN];
__device__ float g_S [BN*128];   // sum_j w_ij * relu(pre_ij)
__device__ float g_c [BN];       // sum_j w_ij
__device__ float g_M [128*128];  // Wm2 @ Wu_bot
__device__ float g_vb[128];      // bm2 @ Wu_bot + bu

typedef unsigned long long u64;

__device__ __forceinline__ u64 dup2(float a) {
    u64 r; unsigned au = __float_as_uint(a);
    asm("mov.b64 %0, {%1, %1};" : "=l"(r) : "r"(au));
    return r;
}
__device__ __forceinline__ u64 add2v(u64 a, u64 b) {
    u64 r; asm("add.rn.f32x2 %0, %1, %2;" : "=l"(r) : "l"(a), "l"(b));
    return r;
}
__device__ __forceinline__ u64 fma2v(u64 a, u64 b, u64 c) {
    u64 r; asm("fma.rn.f32x2 %0, %1, %2, %3;" : "=l"(r) : "l"(a), "l"(b), "l"(c));
    return r;
}
__device__ __forceinline__ void fma2a(u64& acc, u64 a, u64 b) {
    asm("fma.rn.f32x2 %0, %1, %2, %0;" : "+l"(acc) : "l"(a), "l"(b));
}
__device__ __forceinline__ float2 unpk(u64 v) {
    unsigned lo, hi;
    asm("mov.b64 {%0, %1}, %2;" : "=r"(lo), "=r"(hi) : "l"(v));
    return make_float2(__uint_as_float(lo), __uint_as_float(hi));
}
__device__ __forceinline__ u64 pack2(float x, float y) {
    u64 r;
    asm("mov.b64 %0, {%1, %2};" : "=l"(r)
        : "r"(__float_as_uint(x)), "r"(__float_as_uint(y)));
    return r;
}
__device__ __forceinline__ u64 relu2(u64 v) {
    float2 f = unpk(v);
    return pack2(fmaxf(f.x, 0.f), fmaxf(f.y, 0.f));
}

// =======================================================================
// Stage 1: grid 401, block 256, static smem 18KB
//  bid 0..383  : GEMM tiles 16 rows x 128-col panel  (h @ Wm1t/Wm1b/Wut)
//  bid 384..391: g_M tiles  (Wm2 @ Wu_bot)
//  bid 392..399: attention dots
//  bid 400     : vb
// Weights streamed from L1/L2 via LDG; only A tile (duplicated) in smem.
// =======================================================================
__global__ void __launch_bounds__(256) k_stage1(
    const float* __restrict__ h,   const float* __restrict__ Wm1,
    const float* __restrict__ Wa,  const float* __restrict__ Wm2,
    const float* __restrict__ bm2, const float* __restrict__ Wu,
    const float* __restrict__ bu)
{
    __shared__ u64 At2[128*18];     // [k][row-dup], stride 18 (16 used)
    const int bid = blockIdx.x;
    const int t   = threadIdx.x;
    const int wrp = t >> 5, lane = t & 31;

    if (bid < 392) {
        const float *A, *W;
        float* dst;
        if (bid < 384) {
            int mt = bid / 3, p = bid - mt*3;
            A   = h + mt*16*128;
            W   = (p == 0) ? Wm1 : (p == 1) ? (Wm1 + 128*128) : Wu;
            dst = ((p == 0) ? g_A : (p == 1) ? g_Bm : g_P) + mt*16*128;
        } else {
            int mt = bid - 384;
            A   = Wm2 + mt*16*128;
            W   = Wu + 128*128;
            dst = g_M + mt*16*128;
        }
        // fill A tile (16x128) duplicated+transposed
#pragma unroll
        for (int n = 0; n < 2; n++) {
            int idx = t + n*256;            // 0..511
            int r   = idx & 15;
            int kq  = (idx >> 4) * 4;
            float4 v = *(const float4*)&A[r*128 + kq];
            At2[(kq+0)*18 + r] = dup2(v.x);
            At2[(kq+1)*18 + r] = dup2(v.y);
            At2[(kq+2)*18 + r] = dup2(v.z);
            At2[(kq+3)*18 + r] = dup2(v.w);
        }
        __syncthreads();

        u64 a00 = 0ull, a01 = 0ull, a10 = 0ull, a11 = 0ull;
#pragma unroll 4
        for (int k = 0; k < 128; k++) {
            ulonglong2 av = *(const ulonglong2*)&At2[k*18 + wrp*2];
            ulonglong2 wv = *(const ulonglong2*)&W[k*128 + lane*4];
            fma2a(a00, av.x, wv.x); fma2a(a01, av.x, wv.y);
            fma2a(a10, av.y, wv.x); fma2a(a11, av.y, wv.y);
        }
        {
            float2 p = unpk(a00), q = unpk(a01);
            *(float4*)&dst[(wrp*2 + 0)*128 + lane*4] =
                make_float4(p.x, p.y, q.x, q.y);
            p = unpk(a10); q = unpk(a11);
            *(float4*)&dst[(wrp*2 + 1)*128 + lane*4] =
                make_float4(p.x, p.y, q.x, q.y);
        }

    } else if (bid < 400) {
        // dots: 256 rows per block, 32 rows per warp
        const int rowbase = (bid - 392) * 256 + wrp * 32;
        float4 wa1 = *(const float4*)&Wa[lane*4];
        float4 wa2 = *(const float4*)&Wa[128 + lane*4];
#pragma unroll 4
        for (int rr = 0; rr < 32; rr++) {
            int row = rowbase + rr;
            float4 hv = *(const float4*)&h[row*128 + lane*4];
            float sa = hv.x*wa1.x + hv.y*wa1.y + hv.z*wa1.z + hv.w*wa1.w;
            float sb = hv.x*wa2.x + hv.y*wa2.y + hv.z*wa2.z + hv.w*wa2.w;
#pragma unroll
            for (int o = 16; o; o >>= 1) {
                sa += __shfl_xor_sync(0xffffffffu, sa, o);
                sb += __shfl_xor_sync(0xffffffffu, sb, o);
            }
            if (lane == 0) { g_as[row] = sa; g_bs[row] = sb; }
        }
    } else {
        if (t < 128) {
            float acc = bu[t];
#pragma unroll 16
            for (int k = 0; k < 128; k++)
                acc = fmaf(bm2[k], Wu[(128 + k)*128 + t], acc);
            g_vb[t] = acc;
        }
    }
}

// =======================================================================
// k_pair: softmax + weighted relu aggregation -> g_S, g_c
// grid (32,8), block 256, static smem ~33KB -> 4 blocks/SM
// i-tile = 8; B read from global (L1-hot within same-batch blocks)
// =======================================================================
__global__ void __launch_bounds__(256) k_pair(
    const float* __restrict__ dist, const int* __restrict__ adj,
    const float* __restrict__ Wm1,  const float* __restrict__ bm1,
    const float* __restrict__ Wa,   const float* __restrict__ ba)
{
    __shared__ float4 dwsh[8*256];   // [i][j] {d,d,w,w}  32KB
    __shared__ float  bssh[256];

    const int t = threadIdx.x;
    const int b = blockIdx.y, i0 = blockIdx.x * 8;
    const int lane = t & 31, wrp = t >> 5;
    const int cp = t & 63, q = t >> 6;

    bssh[t & 255] = g_bs[b*Nx + (t & 255)];

    // per-thread A rows (+bm1) and wd, packed
    const u64 bmv = *(const u64*)&bm1[cp*2];
    u64 a2[8];
#pragma unroll
    for (int i = 0; i < 8; i++)
        a2[i] = add2v(*(const u64*)&g_A[(size_t)(b*Nx + i0 + i)*128 + cp*2], bmv);
    const u64 wd2 = *(const u64*)&Wm1[256*128 + cp*2];
    __syncthreads();

    // ---- phase 1: warp wrp -> i = i0 + wrp (softmax over j)
    {
        const float wa_d = Wa[256];
        const int ig = b*Nx + i0 + wrp;
        const float a_i = g_as[ig] + ba[0];
        float l[8], dv[8]; int mk[8];
#pragma unroll
        for (int jj = 0; jj < 8; jj++) {
            int j = jj*32 + lane;
            float d = dist[(size_t)ig*Nx + j];
            int   m = adj [(size_t)ig*Nx + j];
            float x = fmaf(d, wa_d, a_i + bssh[j]);
            x = (x >= 0.f) ? x : 0.2f * x;
            l[jj] = m ? x : -1e9f;
            dv[jj] = d; mk[jj] = m;
        }
        float mx = l[0];
#pragma unroll
        for (int jj = 1; jj < 8; jj++) mx = fmaxf(mx, l[jj]);
#pragma unroll
        for (int o = 16; o; o >>= 1) mx = fmaxf(mx, __shfl_xor_sync(0xffffffffu, mx, o));
        float sum = 0.f, cs = 0.f;
#pragma unroll
        for (int jj = 0; jj < 8; jj++) {
            float e = expf(l[jj] - mx);
            l[jj] = e; sum += e;
            cs += mk[jj] ? e : 0.f;
        }
#pragma unroll
        for (int o = 16; o; o >>= 1) {
            sum += __shfl_xor_sync(0xffffffffu, sum, o);
            cs  += __shfl_xor_sync(0xffffffffu, cs,  o);
        }
        float inv = 1.f / sum;
#pragma unroll
        for (int jj = 0; jj < 8; jj++) {
            int j = jj*32 + lane;
            float w = mk[jj] ? l[jj]*inv : 0.f;
            dwsh[wrp*256 + j] = make_float4(dv[jj], dv[jj], w, w);
        }
        if (lane == 0) g_c[ig] = cs * inv;
    }
    __syncthreads();

    // ---- phase 2: thread (cp, q) covers j = q + 4*jj
    u64 acc2[8];
#pragma unroll
    for (int i = 0; i < 8; i++) acc2[i] = 0ull;

    const ulonglong2* dwp = (const ulonglong2*)dwsh;
    const float* Bbase = g_Bm + (size_t)b*Nx*128 + cp*2;
    u64 bnext = *(const u64*)&Bbase[(size_t)q*128];
#pragma unroll 1
    for (int jj = 0; jj < 64; jj++) {
        const int j = jj*4 + q;
        u64 b2 = bnext;
        if (jj < 63) bnext = *(const u64*)&Bbase[(size_t)(j + 4)*128];
#pragma unroll
        for (int i = 0; i < 8; i++) {
            ulonglong2 dw = dwp[i*256 + j];     // warp-broadcast LDS.128
            u64 x = fma2v(dw.x, wd2, add2v(a2[i], b2));
            acc2[i] = fma2v(dw.y, relu2(x), acc2[i]);
        }
    }
    __syncthreads();   // dwsh reads done

    // ---- reduce over q (4 partials) via smem overlay
    u64* part = (u64*)dwsh;   // [8][4][64]
#pragma unroll
    for (int i = 0; i < 8; i++) part[(i*4 + q)*64 + cp] = acc2[i];
    __syncthreads();
#pragma unroll
    for (int rep = 0; rep < 2; rep++) {
        int idx = t + rep*256;        // 0..511
        int i = idx >> 6, c2 = idx & 63;
        float2 s = make_float2(0.f, 0.f);
#pragma unroll
        for (int qq = 0; qq < 4; qq++) {
            float2 v = unpk(part[(i*4 + qq)*64 + c2]);
            s.x += v.x; s.y += v.y;
        }
        *(float2*)&g_S[(size_t)(b*Nx + i0 + i)*128 + c2*2] = s;
    }
}

// =======================================================================
// k_out: out = relu( g_P + S@M + g_c*vb )
// grid 128, block 256, 16 rows/block; M streamed via LDG
// =======================================================================
__global__ void __launch_bounds__(256) k_out(float* __restrict__ out)
{
    __shared__ u64 St2[128*18];
    const int t = threadIdx.x;
    const int wrp = t >> 5, lane = t & 31;
    const int row0 = blockIdx.x * 16;

#pragma unroll
    for (int n = 0; n < 2; n++) {
        int idx = t + n*256;
        int r   = idx & 15;
        int kq  = (idx >> 4) * 4;
        float4 v = *(const float4*)&g_S[(size_t)(row0 + r)*128 + kq];
        St2[(kq+0)*18 + r] = dup2(v.x);
        St2[(kq+1)*18 + r] = dup2(v.y);
        St2[(kq+2)*18 + r] = dup2(v.z);
        St2[(kq+3)*18 + r] = dup2(v.w);
    }
    __syncthreads();

    u64 a00 = 0ull, a01 = 0ull, a10 = 0ull, a11 = 0ull;
#pragma unroll 4
    for (int k = 0; k < 128; k++) {
        ulonglong2 av = *(const ulonglong2*)&St2[k*18 + wrp*2];
        ulonglong2 wv = *(const ulonglong2*)&g_M[k*128 + lane*4];
        fma2a(a00, av.x, wv.x); fma2a(a01, av.x, wv.y);
        fma2a(a10, av.y, wv.x); fma2a(a11, av.y, wv.y);
    }

    float4 vb4 = *(const float4*)&g_vb[lane*4];
#pragma unroll
    for (int r = 0; r < 2; r++) {
        int row = row0 + wrp*2 + r;
        float cr = g_c[row];
        float4 pv = *(const float4*)&g_P[(size_t)row*128 + lane*4];
        float2 p = unpk(r ? a10 : a00), qv = unpk(r ? a11 : a01);
        float4 o;
        o.x = fmaxf(pv.x + fmaf(cr, vb4.x, p.x),  0.f);
        o.y = fmaxf(pv.y + fmaf(cr, vb4.y, p.y),  0.f);
        o.z = fmaxf(pv.z + fmaf(cr, vb4.z, qv.x), 0.f);
        o.w = fmaxf(pv.w + fmaf(cr, vb4.w, qv.y), 0.f);
        *(float4*)&out[(size_t)row*128 + lane*4] = o;
    }
}

// =======================================================================
extern "C" void kernel_launch(void* const* d_in, const int* in_sizes, int n_in,
                              void* d_out, int out_size)
{
    const float* h    = (const float*)d_in[0];
    const int*   adj  = (const int*)  d_in[1];
    const float* dist = (const float*)d_in[2];
    const float* Wm1  = (const float*)d_in[3];
    const float* bm1  = (const float*)d_in[4];
    const float* Wm2  = (const float*)d_in[5];
    const float* bm2  = (const float*)d_in[6];
    const float* Wa   = (const float*)d_in[7];
    const float* ba   = (const float*)d_in[8];
    const float* Wu   = (const float*)d_in[9];
    const float* bu   = (const float*)d_in[10];
    float* out = (float*)d_out;

    k_stage1<<<401, 256>>>(h, Wm1, Wa, Wm2, bm2, Wu, bu);
    k_pair  <<<dim3(32, 8), 256>>>(dist, adj, Wm1, bm1, Wa, ba);
    k_out   <<<128, 256>>>(out);
}

// round 7
// speedup vs baseline: 1.0342x; 1.0342x over previous
#include <cuda_runtime.h>
#include <math.h>

#define Nx   256
#define BN   2048      // 8*256

// ---------------- scratch ----------------
__device__ float g_A [BN*128];   // h @ Wm1[0:128]
__device__ float g_Bm[BN*128];   // h @ Wm1[128:256]
__device__ float g_P [BN*128];   // h @ Wu_top
__device__ float g_as[BN];
__device__ float g_bs[BN];
__device__ float g_S [BN*128];   // sum_j w_ij * relu(pre_ij)
__device__ float g_c [BN];       // sum_j w_ij
__device__ float g_M [128*128];  // Wm2 @ Wu_bot
__device__ float g_vb[128];      // bm2 @ Wu_bot + bu

typedef unsigned long long u64;

__device__ __forceinline__ u64 dup2(float a) {
    u64 r; unsigned au = __float_as_uint(a);
    asm("mov.b64 %0, {%1, %1};" : "=l"(r) : "r"(au));
    return r;
}
__device__ __forceinline__ u64 add2v(u64 a, u64 b) {
    u64 r; asm("add.rn.f32x2 %0, %1, %2;" : "=l"(r) : "l"(a), "l"(b));
    return r;
}
__device__ __forceinline__ u64 fma2v(u64 a, u64 b, u64 c) {
    u64 r; asm("fma.rn.f32x2 %0, %1, %2, %3;" : "=l"(r) : "l"(a), "l"(b), "l"(c));
    return r;
}
__device__ __forceinline__ void fma2a(u64& acc, u64 a, u64 b) {
    asm("fma.rn.f32x2 %0, %1, %2, %0;" : "+l"(acc) : "l"(a), "l"(b));
}
__device__ __forceinline__ float2 unpk(u64 v) {
    unsigned lo, hi;
    asm("mov.b64 {%0, %1}, %2;" : "=r"(lo), "=r"(hi) : "l"(v));
    return make_float2(__uint_as_float(lo), __uint_as_float(hi));
}
__device__ __forceinline__ u64 pack2(float x, float y) {
    u64 r;
    asm("mov.b64 %0, {%1, %2};" : "=l"(r)
        : "r"(__float_as_uint(x)), "r"(__float_as_uint(y)));
    return r;
}
__device__ __forceinline__ u64 relu2(u64 v) {
    float2 f = unpk(v);
    return pack2(fmaxf(f.x, 0.f), fmaxf(f.y, 0.f));
}

// =======================================================================
// Stage 1: grid 107, block 256, dyn smem 102400
//  bid 0..95 : h row-tile (64) x one 128-col panel (Wm1t / Wm1b / Wut)
//  bid 96,97 : Wm2 @ Wu_bot -> g_M (64-row tiles)
//  bid 98..105: attention dots (256 rows each)
//  bid 106   : vb
//  micro 4x8 in f32x2: bytes/MAC = 1.5 (crossbar ~= fma pipe)
// =======================================================================
#define S1_SMEM ((128*132 + 128*68) * 4)

__global__ void __launch_bounds__(256) k_stage1(
    const float* __restrict__ h,   const float* __restrict__ Wm1,
    const float* __restrict__ Wa,  const float* __restrict__ Wm2,
    const float* __restrict__ bm2, const float* __restrict__ Wu,
    const float* __restrict__ bu)
{
    extern __shared__ float sm[];
    float* Ws = sm;                 // [128][132]
    float* At = sm + 128*132;       // [128][68] transposed A
    const int bid = blockIdx.x;
    const int t   = threadIdx.x;

    if (bid < 98) {
        const float *A, *W;
        float* dst;
        if (bid < 96) {
            int mt = bid / 3, p = bid - mt*3;
            A   = h + mt*64*128;
            W   = (p == 0) ? Wm1 : (p == 1) ? (Wm1 + 128*128) : Wu;
            dst = ((p == 0) ? g_A : (p == 1) ? g_Bm : g_P) + mt*64*128;
        } else {
            A   = Wm2 + (bid - 96)*64*128;
            W   = Wu + 128*128;
            dst = g_M + (bid - 96)*64*128;
        }
        // W panel 128x128
#pragma unroll
        for (int n = 0; n < 16; n++) {
            int idx = t + n*256;
            int wk = idx >> 5, wn = (idx & 31) * 4;
            *(float4*)&Ws[wk*132 + wn] = *(const float4*)&W[wk*128 + wn];
        }
        // A tile 64x128 -> transposed
#pragma unroll
        for (int n = 0; n < 8; n++) {
            int idx = t + n*256;            // 0..2047
            int r = idx >> 5, kq = (idx & 31) * 4;
            float4 v = *(const float4*)&A[r*128 + kq];
            At[(kq+0)*68 + r] = v.x; At[(kq+1)*68 + r] = v.y;
            At[(kq+2)*68 + r] = v.z; At[(kq+3)*68 + r] = v.w;
        }
        __syncthreads();

        const int ty = t >> 4, cx = t & 15;   // rows ty*4.., cols cx*8..
        u64 acc[4][4];
#pragma unroll
        for (int r = 0; r < 4; r++)
#pragma unroll
            for (int c = 0; c < 4; c++) acc[r][c] = 0ull;

#pragma unroll 4
        for (int k = 0; k < 128; k++) {
            float4 a4 = *(const float4*)&At[k*68 + ty*4];       // broadcast
            ulonglong2 w0 = *(const ulonglong2*)&Ws[k*132 + cx*8];
            ulonglong2 w1 = *(const ulonglong2*)&Ws[k*132 + cx*8 + 4];
            u64 aa;
            aa = dup2(a4.x);
            fma2a(acc[0][0], aa, w0.x); fma2a(acc[0][1], aa, w0.y);
            fma2a(acc[0][2], aa, w1.x); fma2a(acc[0][3], aa, w1.y);
            aa = dup2(a4.y);
            fma2a(acc[1][0], aa, w0.x); fma2a(acc[1][1], aa, w0.y);
            fma2a(acc[1][2], aa, w1.x); fma2a(acc[1][3], aa, w1.y);
            aa = dup2(a4.z);
            fma2a(acc[2][0], aa, w0.x); fma2a(acc[2][1], aa, w0.y);
            fma2a(acc[2][2], aa, w1.x); fma2a(acc[2][3], aa, w1.y);
            aa = dup2(a4.w);
            fma2a(acc[3][0], aa, w0.x); fma2a(acc[3][1], aa, w0.y);
            fma2a(acc[3][2], aa, w1.x); fma2a(acc[3][3], aa, w1.y);
        }
#pragma unroll
        for (int r = 0; r < 4; r++) {
            float2 p0 = unpk(acc[r][0]), p1 = unpk(acc[r][1]);
            float2 p2 = unpk(acc[r][2]), p3 = unpk(acc[r][3]);
            *(float4*)&dst[(ty*4 + r)*128 + cx*8] =
                make_float4(p0.x, p0.y, p1.x, p1.y);
            *(float4*)&dst[(ty*4 + r)*128 + cx*8 + 4] =
                make_float4(p2.x, p2.y, p3.x, p3.y);
        }

    } else if (bid < 106) {
        const int wrp = t >> 5, lane = t & 31;
        const int rowbase = (bid - 98) * 256 + wrp * 32;
        float4 wa1 = *(const float4*)&Wa[lane*4];
        float4 wa2 = *(const float4*)&Wa[128 + lane*4];
#pragma unroll 4
        for (int rr = 0; rr < 32; rr++) {
            int row = rowbase + rr;
            float4 hv = *(const float4*)&h[row*128 + lane*4];
            float sa = hv.x*wa1.x + hv.y*wa1.y + hv.z*wa1.z + hv.w*wa1.w;
            float sb = hv.x*wa2.x + hv.y*wa2.y + hv.z*wa2.z + hv.w*wa2.w;
#pragma unroll
            for (int o = 16; o; o >>= 1) {
                sa += __shfl_xor_sync(0xffffffffu, sa, o);
                sb += __shfl_xor_sync(0xffffffffu, sb, o);
            }
            if (lane == 0) { g_as[row] = sa; g_bs[row] = sb; }
        }
    } else {
        if (t < 128) {
            float acc = bu[t];
#pragma unroll 16
            for (int k = 0; k < 128; k++)
                acc = fmaf(bm2[k], Wu[(128 + k)*128 + t], acc);
            g_vb[t] = acc;
        }
    }
}

// =======================================================================
// k_pair: softmax + COMPACTED weighted relu aggregation -> g_S, g_c
// grid (16,8), block 512, dyn smem 222272
//  phase1: warp i computes softmax, compacts nonzero-adj j's
//  phase2: thread (cp in 32, q in 16) covers 4 channels, strides j-slots
// =======================================================================
#define PAIR_SMEM ((32768 + 16384 + 4096 + 2048 + 256 + 16) * 4)

__global__ void __launch_bounds__(512, 1) k_pair(
    const float* __restrict__ dist, const int* __restrict__ adj,
    const float* __restrict__ Wm1,  const float* __restrict__ bm1,
    const float* __restrict__ Wa,   const float* __restrict__ ba)
{
    extern __shared__ float sm[];
    float*      Bsh   = sm;                                  // 128KB
    ulonglong2* recsh = (ulonglong2*)(sm + 32768);           // [16][256] {dd,ww}
    int*        jsh   = (int*)(sm + 32768 + 16384);          // [16][256]
    float*      Ash   = sm + 32768 + 16384 + 4096;           // [16][128] A+bm1
    float*      bssh  = Ash + 2048;                          // 256
    int*        nnzsh = (int*)(bssh + 256);                  // 16

    const int t = threadIdx.x;
    const int b = blockIdx.y, i0 = blockIdx.x * 16;
    const int lane = t & 31, wrp = t >> 5;

    // ---- fills
    {
        const float4* src = (const float4*)(g_Bm + (size_t)b*Nx*128);
        float4* d4 = (float4*)Bsh;
#pragma unroll
        for (int k = 0; k < 16; k++) d4[t + k*512] = src[t + k*512];
    }
#pragma unroll
    for (int k = 0; k < 4; k++) {
        int idx = t + k*512;
        Ash[idx] = g_A[(size_t)(b*Nx + i0)*128 + idx] + bm1[idx & 127];
    }
    if (t < 256) bssh[t] = g_bs[b*Nx + t];
    __syncthreads();

    // ---- phase 1: warp wrp -> i = i0 + wrp; softmax + compaction
    {
        const float wa_d = Wa[256];
        const int ig = b*Nx + i0 + wrp;
        const float a_i = g_as[ig] + ba[0];
        float l[8], dv[8]; int mk[8];
#pragma unroll
        for (int jj = 0; jj < 8; jj++) {
            int j = jj*32 + lane;
            float d = dist[(size_t)ig*Nx + j];
            int   m = adj [(size_t)ig*Nx + j];
            float x = fmaf(d, wa_d, a_i + bssh[j]);
            x = (x >= 0.f) ? x : 0.2f * x;
            l[jj] = m ? x : -1e9f;
            dv[jj] = d; mk[jj] = m;
        }
        float mx = l[0];
#pragma unroll
        for (int jj = 1; jj < 8; jj++) mx = fmaxf(mx, l[jj]);
#pragma unroll
        for (int o = 16; o; o >>= 1) mx = fmaxf(mx, __shfl_xor_sync(0xffffffffu, mx, o));
        float sum = 0.f, cs = 0.f;
#pragma unroll
        for (int jj = 0; jj < 8; jj++) {
            float e = expf(l[jj] - mx);
            l[jj] = e; sum += e;
            cs += mk[jj] ? e : 0.f;
        }
#pragma unroll
        for (int o = 16; o; o >>= 1) {
            sum += __shfl_xor_sync(0xffffffffu, sum, o);
            cs  += __shfl_xor_sync(0xffffffffu, cs,  o);
        }
        const float inv = 1.f / sum;
        int nbase = 0;
#pragma unroll
        for (int jj = 0; jj < 8; jj++) {
            unsigned bal = __ballot_sync(0xffffffffu, mk[jj] != 0);
            if (mk[jj]) {
                int pos = nbase + __popc(bal & ((1u << lane) - 1u));
                ulonglong2 rec;
                rec.x = dup2(dv[jj]);
                rec.y = dup2(l[jj] * inv);
                recsh[wrp*256 + pos] = rec;
                jsh  [wrp*256 + pos] = jj*32 + lane;
            }
            nbase += __popc(bal);
        }
        if (lane == 0) { nnzsh[wrp] = nbase; g_c[ig] = cs * inv; }
    }
    __syncthreads();

    // ---- phase 2: thread covers 4 channels (cp), j-lane q (= warp)
    const int cp = t & 31, q = t >> 5;
    const ulonglong2 wd4 = *(const ulonglong2*)&Wm1[256*128 + cp*4];
    const ulonglong2* BshU = (const ulonglong2*)Bsh;   // [j][32] 16B elems

    u64 accx[16], accy[16];
#pragma unroll
    for (int i = 0; i < 16; i++) { accx[i] = 0ull; accy[i] = 0ull; }

#pragma unroll
    for (int i = 0; i < 16; i++) {
        const ulonglong2 av = *(const ulonglong2*)&Ash[i*128 + cp*4];
        const int n = nnzsh[i];
        for (int s = q; s < n; s += 16) {
            ulonglong2 rec = recsh[i*256 + s];   // broadcast
            int j = jsh[i*256 + s];              // broadcast
            ulonglong2 b2 = BshU[j*32 + cp];     // coalesced
            u64 x0 = fma2v(rec.x, wd4.x, add2v(av.x, b2.x));
            u64 x1 = fma2v(rec.x, wd4.y, add2v(av.y, b2.y));
            accx[i] = fma2v(rec.y, relu2(x0), accx[i]);
            accy[i] = fma2v(rec.y, relu2(x1), accy[i]);
        }
    }
    __syncthreads();   // done reading Bsh / recsh

    // ---- reduce over 16 q-lanes via overlay on Bsh
    ulonglong2* part = (ulonglong2*)Bsh;   // [16][16][32]
#pragma unroll
    for (int i = 0; i < 16; i++) {
        ulonglong2 v; v.x = accx[i]; v.y = accy[i];
        part[(i*16 + q)*32 + cp] = v;
    }
    __syncthreads();
    {
        const int i = t >> 5, c4 = t & 31;
        u64 sx = 0ull, sy = 0ull;
#pragma unroll
        for (int qq = 0; qq < 16; qq++) {
            ulonglong2 v = part[(i*16 + qq)*32 + c4];
            sx = add2v(sx, v.x); sy = add2v(sy, v.y);
        }
        float2 p = unpk(sx), r = unpk(sy);
        *(float4*)&g_S[(size_t)(b*Nx + i0 + i)*128 + c4*4] =
            make_float4(p.x, p.y, r.x, r.y);
    }
}

// =======================================================================
// k_out: out = relu( g_P + S@M + g_c*vb )
// grid 128, block 256, 16 rows/block, M in smem, dyn smem 86016
// =======================================================================
#define KO_SMEM ((128*132) * 4 + (128*18) * 8)

__global__ void __launch_bounds__(256) k_out(float* __restrict__ out)
{
    extern __shared__ float sm[];
    float* Ms  = sm;                      // [128][132]
    u64*   St2 = (u64*)(sm + 128*132);    // [128][18] dup'd S
    const int t = threadIdx.x;
    const int row0 = blockIdx.x * 16;

#pragma unroll
    for (int n = 0; n < 16; n++) {
        int idx = t + n*256;
        int wk = idx >> 5, wn = (idx & 31) * 4;
        *(float4*)&Ms[wk*132 + wn] = *(const float4*)&g_M[wk*128 + wn];
    }
#pragma unroll
    for (int n = 0; n < 2; n++) {
        int idx = t + n*256;
        int r   = idx & 15;
        int kq  = (idx >> 4) * 4;
        float4 v = *(const float4*)&g_S[(size_t)(row0 + r)*128 + kq];
        St2[(kq+0)*18 + r] = dup2(v.x);
        St2[(kq+1)*18 + r] = dup2(v.y);
        St2[(kq+2)*18 + r] = dup2(v.z);
        St2[(kq+3)*18 + r] = dup2(v.w);
    }
    __syncthreads();

    const int ry = t >> 5, cx = t & 31;   // rows ry*2.., cols cx*4..
    u64 a00 = 0ull, a01 = 0ull, a10 = 0ull, a11 = 0ull;
#pragma unroll 4
    for (int k = 0; k < 128; k++) {
        ulonglong2 av = *(const ulonglong2*)&St2[k*18 + ry*2];   // broadcast
        ulonglong2 wv = *(const ulonglong2*)&Ms[k*132 + cx*4];
        fma2a(a00, av.x, wv.x); fma2a(a01, av.x, wv.y);
        fma2a(a10, av.y, wv.x); fma2a(a11, av.y, wv.y);
    }

    float4 vb4 = *(const float4*)&g_vb[cx*4];
#pragma unroll
    for (int r = 0; r < 2; r++) {
        int row = row0 + ry*2 + r;
        float cr = g_c[row];
        float4 pv = *(const float4*)&g_P[(size_t)row*128 + cx*4];
        float2 p = unpk(r ? a10 : a00), qv = unpk(r ? a11 : a01);
        float4 o;
        o.x = fmaxf(pv.x + fmaf(cr, vb4.x, p.x),  0.f);
        o.y = fmaxf(pv.y + fmaf(cr, vb4.y, p.y),  0.f);
        o.z = fmaxf(pv.z + fmaf(cr, vb4.z, qv.x), 0.f);
        o.w = fmaxf(pv.w + fmaf(cr, vb4.w, qv.y), 0.f);
        *(float4*)&out[(size_t)row*128 + cx*4] = o;
    }
}

// =======================================================================
extern "C" void kernel_launch(void* const* d_in, const int* in_sizes, int n_in,
                              void* d_out, int out_size)
{
    const float* h    = (const float*)d_in[0];
    const int*   adj  = (const int*)  d_in[1];
    const float* dist = (const float*)d_in[2];
    const float* Wm1  = (const float*)d_in[3];
    const float* bm1  = (const float*)d_in[4];
    const float* Wm2  = (const float*)d_in[5];
    const float* bm2  = (const float*)d_in[6];
    const float* Wa   = (const float*)d_in[7];
    const float* ba   = (const float*)d_in[8];
    const float* Wu   = (const float*)d_in[9];
    const float* bu   = (const float*)d_in[10];
    float* out = (float*)d_out;

    cudaFuncSetAttribute(k_stage1, cudaFuncAttributeMaxDynamicSharedMemorySize,
                         S1_SMEM);
    cudaFuncSetAttribute(k_pair, cudaFuncAttributeMaxDynamicSharedMemorySize,
                         PAIR_SMEM);
    cudaFuncSetAttribute(k_out, cudaFuncAttributeMaxDynamicSharedMemorySize,
                         KO_SMEM);

    k_stage1<<<107, 256, S1_SMEM>>>(h, Wm1, Wa, Wm2, bm2, Wu, bu);
    k_pair  <<<dim3(16, 8), 512, PAIR_SMEM>>>(dist, adj, Wm1, bm1, Wa, ba);
    k_out   <<<128, 256, KO_SMEM>>>(out);
}

// round 8
// speedup vs baseline: 1.4950x; 1.4456x over previous
#include <cuda_runtime.h>
#include <math.h>

#define Nx   256
#define BN   2048      // 8*256

// ---------------- scratch ----------------
__device__ float g_A [BN*128];   // h @ Wm1[0:128]
__device__ float g_Bm[BN*128];   // h @ Wm1[128:256]
__device__ float g_P [BN*128];   // h @ Wu_top
__device__ float g_as[BN];
__device__ float g_bs[BN];
__device__ float g_S [BN*128];   // sum_j w_ij * relu(pre_ij)
__device__ float g_c [BN];       // sum_j w_ij
__device__ float g_M [128*128];  // Wm2 @ Wu_bot
__device__ float g_vb[128];      // bm2 @ Wu_bot + bu

typedef unsigned long long u64;

__device__ __forceinline__ u64 dup2(float a) {
    u64 r; unsigned au = __float_as_uint(a);
    asm("mov.b64 %0, {%1, %1};" : "=l"(r) : "r"(au));
    return r;
}
__device__ __forceinline__ u64 add2v(u64 a, u64 b) {
    u64 r; asm("add.rn.f32x2 %0, %1, %2;" : "=l"(r) : "l"(a), "l"(b));
    return r;
}
__device__ __forceinline__ u64 fma2v(u64 a, u64 b, u64 c) {
    u64 r; asm("fma.rn.f32x2 %0, %1, %2, %3;" : "=l"(r) : "l"(a), "l"(b), "l"(c));
    return r;
}
__device__ __forceinline__ void fma2a(u64& acc, u64 a, u64 b) {
    asm("fma.rn.f32x2 %0, %1, %2, %0;" : "+l"(acc) : "l"(a), "l"(b));
}
__device__ __forceinline__ float2 unpk(u64 v) {
    unsigned lo, hi;
    asm("mov.b64 {%0, %1}, %2;" : "=r"(lo), "=r"(hi) : "l"(v));
    return make_float2(__uint_as_float(lo), __uint_as_float(hi));
}
__device__ __forceinline__ u64 pack2(float x, float y) {
    u64 r;
    asm("mov.b64 %0, {%1, %2};" : "=l"(r)
        : "r"(__float_as_uint(x)), "r"(__float_as_uint(y)));
    return r;
}
__device__ __forceinline__ u64 relu2(u64 v) {
    float2 f = unpk(v);
    return pack2(fmaxf(f.x, 0.f), fmaxf(f.y, 0.f));
}

// =======================================================================
// Stage 1: grid 205, block 256, dyn smem 69632  (R3-proven shape)
//  bid 0..191  : 64x64 tiles of h @ [Wm1t|Wm1b|Wut]  (mt 0..31, nt 0..5)
//  bid 192..195: 64x64 tiles of Wm2 @ Wu_bot -> g_M
//  bid 196..203: attention dots (256 rows each)
//  bid 204     : vb
// =======================================================================
#define S1_SMEM (2*128*68*4)

__global__ void __launch_bounds__(256) k_stage1(
    const float* __restrict__ h,   const float* __restrict__ Wm1,
    const float* __restrict__ Wa,  const float* __restrict__ Wm2,
    const float* __restrict__ bm2, const float* __restrict__ Wu,
    const float* __restrict__ bu)
{
    extern __shared__ float sm[];
    const int bid = blockIdx.x;
    const int t   = threadIdx.x;

    if (bid < 196) {
        float* At = sm;              // [128][68] k-major transposed A
        float* Ws = sm + 128*68;     // [128][68] W tile (128 x 64)
        const float *A, *W;
        float* dst;
        if (bid < 192) {
            int mt = bid / 6, nt = bid - mt*6;
            int p = nt >> 1, col0 = (nt & 1) * 64;
            A = h + mt*64*128;
            W = ((p == 0) ? Wm1 : (p == 1) ? (Wm1 + 128*128) : Wu) + col0;
            dst = ((p == 0) ? g_A : (p == 1) ? g_Bm : g_P) + mt*64*128 + col0;
        } else {
            int bb = bid - 192;
            int mm = bb >> 1, col0 = (bb & 1) * 64;
            A = Wm2 + mm*64*128;
            W = Wu + 128*128 + col0;
            dst = g_M + mm*64*128 + col0;
        }
        // A tile 64x128 -> transposed
#pragma unroll
        for (int n = 0; n < 8; n++) {
            int l = t + n*256;            // 0..2047 quads
            int r = l >> 5, kq = (l & 31) * 4;
            float4 v = *(const float4*)&A[r*128 + kq];
            At[(kq+0)*68 + r] = v.x; At[(kq+1)*68 + r] = v.y;
            At[(kq+2)*68 + r] = v.z; At[(kq+3)*68 + r] = v.w;
        }
        // W tile 128x64
#pragma unroll
        for (int n = 0; n < 8; n++) {
            int l = t + n*256;
            int wk = l >> 4, wn = (l & 15) * 4;
            *(float4*)&Ws[wk*68 + wn] = *(const float4*)&W[wk*128 + wn];
        }
        __syncthreads();

        const int ty = t >> 4, tx = t & 15;
        u64 acc[4][2];
#pragma unroll
        for (int r = 0; r < 4; r++) { acc[r][0] = 0ull; acc[r][1] = 0ull; }

#pragma unroll 8
        for (int k = 0; k < 128; k++) {
            float4 a4 = *(const float4*)&At[k*68 + ty*4];
            ulonglong2 bb = *(const ulonglong2*)&Ws[k*68 + tx*4];
            u64 aa;
            aa = dup2(a4.x); fma2a(acc[0][0], aa, bb.x); fma2a(acc[0][1], aa, bb.y);
            aa = dup2(a4.y); fma2a(acc[1][0], aa, bb.x); fma2a(acc[1][1], aa, bb.y);
            aa = dup2(a4.z); fma2a(acc[2][0], aa, bb.x); fma2a(acc[2][1], aa, bb.y);
            aa = dup2(a4.w); fma2a(acc[3][0], aa, bb.x); fma2a(acc[3][1], aa, bb.y);
        }
#pragma unroll
        for (int r = 0; r < 4; r++) {
            float2 p = unpk(acc[r][0]), q = unpk(acc[r][1]);
            *(float4*)&dst[(ty*4 + r)*128 + tx*4] =
                make_float4(p.x, p.y, q.x, q.y);
        }

    } else if (bid < 204) {
        const int wrp = t >> 5, lane = t & 31;
        const int rowbase = (bid - 196) * 256 + wrp * 32;
        float4 wa1 = *(const float4*)&Wa[lane*4];
        float4 wa2 = *(const float4*)&Wa[128 + lane*4];
#pragma unroll 4
        for (int rr = 0; rr < 32; rr++) {
            int row = rowbase + rr;
            float4 hv = *(const float4*)&h[row*128 + lane*4];
            float sa = hv.x*wa1.x + hv.y*wa1.y + hv.z*wa1.z + hv.w*wa1.w;
            float sb = hv.x*wa2.x + hv.y*wa2.y + hv.z*wa2.z + hv.w*wa2.w;
#pragma unroll
            for (int o = 16; o; o >>= 1) {
                sa += __shfl_xor_sync(0xffffffffu, sa, o);
                sb += __shfl_xor_sync(0xffffffffu, sb, o);
            }
            if (lane == 0) { g_as[row] = sa; g_bs[row] = sb; }
        }
    } else {
        if (t < 128) {
            float acc = bu[t];
#pragma unroll 16
            for (int k = 0; k < 128; k++)
                acc = fmaf(bm2[k], Wu[(128 + k)*128 + t], acc);
            g_vb[t] = acc;
        }
    }
}

// =======================================================================
// k_pair: softmax + weighted relu aggregation -> g_S, g_c
// grid (16,8), block 1024 (8 warps/SMSP!), dyn smem 201728
// phase2: thread (cp 0..63, q 0..15); i-half = q&1, j-slot = q>>1
// =======================================================================
#define PAIR_SMEM ((32768 + 16384 + 2048 + 256) * 4)

__global__ void __launch_bounds__(1024, 1) k_pair(
    const float* __restrict__ dist, const int* __restrict__ adj,
    const float* __restrict__ Wm1,  const float* __restrict__ bm1,
    const float* __restrict__ Wa,   const float* __restrict__ ba)
{
    extern __shared__ float sm[];
    float*  Bsh  = sm;                       // [256][128]  128KB
    float4* dwsh = (float4*)(sm + 32768);    // [16][256] {d,d,w,w}  64KB
    float*  Ash  = sm + 32768 + 16384;       // [16][128] A + bm1
    float*  bssh = Ash + 2048;               // 256

    const int t = threadIdx.x;
    const int b = blockIdx.y, i0 = blockIdx.x * 16;
    const int lane = t & 31, wrp = t >> 5;

    // ---- fills (1024 threads)
    {
        const float4* src = (const float4*)(g_Bm + (size_t)b*Nx*128);
        float4* d4 = (float4*)Bsh;
#pragma unroll
        for (int k = 0; k < 8; k++) d4[t + k*1024] = src[t + k*1024];
    }
#pragma unroll
    for (int k = 0; k < 2; k++) {
        int idx = t + k*1024;
        Ash[idx] = g_A[(size_t)(b*Nx + i0)*128 + idx] + bm1[idx & 127];
    }
    if (t < 256) bssh[t] = g_bs[b*Nx + t];
    __syncthreads();

    // ---- phase 1: warps 0..15 -> i = i0 + wrp (softmax over j)
    if (wrp < 16) {
        const float wa_d = Wa[256];
        const int ig = b*Nx + i0 + wrp;
        const float a_i = g_as[ig] + ba[0];
        float l[8], dv[8]; int mk[8];
#pragma unroll
        for (int jj = 0; jj < 8; jj++) {
            int j = jj*32 + lane;
            float d = dist[(size_t)ig*Nx + j];
            int   m = adj [(size_t)ig*Nx + j];
            float x = fmaf(d, wa_d, a_i + bssh[j]);
            x = (x >= 0.f) ? x : 0.2f * x;
            l[jj] = m ? x : -1e9f;
            dv[jj] = d; mk[jj] = m;
        }
        float mx = l[0];
#pragma unroll
        for (int jj = 1; jj < 8; jj++) mx = fmaxf(mx, l[jj]);
#pragma unroll
        for (int o = 16; o; o >>= 1) mx = fmaxf(mx, __shfl_xor_sync(0xffffffffu, mx, o));
        float sum = 0.f, cs = 0.f;
#pragma unroll
        for (int jj = 0; jj < 8; jj++) {
            float e = expf(l[jj] - mx);
            l[jj] = e; sum += e;
            cs += mk[jj] ? e : 0.f;
        }
#pragma unroll
        for (int o = 16; o; o >>= 1) {
            sum += __shfl_xor_sync(0xffffffffu, sum, o);
            cs  += __shfl_xor_sync(0xffffffffu, cs,  o);
        }
        float inv = 1.f / sum;
#pragma unroll
        for (int jj = 0; jj < 8; jj++) {
            int j = jj*32 + lane;
            float w = mk[jj] ? l[jj]*inv : 0.f;
            dwsh[wrp*256 + j] = make_float4(dv[jj], dv[jj], w, w);
        }
        if (lane == 0) g_c[ig] = cs * inv;
    }
    __syncthreads();

    // ---- phase 2: thread (cp, q); i in [ (q&1)*8, +8 ), j = jj*8 + (q>>1)
    const int cp  = t & 63;
    const int q   = t >> 6;
    const int ig8 = (q & 1) * 8;
    const int qh  = q >> 1;

    u64 a2[8], acc2[8];
#pragma unroll
    for (int i = 0; i < 8; i++) {
        a2[i]   = *(const u64*)&Ash[(ig8 + i)*128 + cp*2];
        acc2[i] = 0ull;
    }
    const u64 wd2 = *(const u64*)&Wm1[256*128 + cp*2];

    const ulonglong2* dwp = (const ulonglong2*)dwsh;
#pragma unroll 1
    for (int jj = 0; jj < 32; jj++) {
        const int j = jj*8 + qh;
        u64 b2 = *(const u64*)&Bsh[j*128 + cp*2];
#pragma unroll
        for (int i = 0; i < 8; i++) {
            ulonglong2 dw = dwp[(ig8 + i)*256 + j];   // warp-broadcast
            u64 x = fma2v(dw.x, wd2, add2v(a2[i], b2));
            acc2[i] = fma2v(dw.y, relu2(x), acc2[i]);
        }
    }
    __syncthreads();   // done reading Bsh & dwsh

    // ---- reduce over 8 j-slot partials via overlay on Bsh
    u64* part = (u64*)Bsh;   // [16][8][64] = 64KB
#pragma unroll
    for (int i = 0; i < 8; i++)
        part[((ig8 + i)*8 + qh)*64 + cp] = acc2[i];
    __syncthreads();
    {
        const int i = t >> 6, c2 = t & 63;
        float2 s = make_float2(0.f, 0.f);
#pragma unroll
        for (int qq = 0; qq < 8; qq++) {
            float2 v = unpk(part[(i*8 + qq)*64 + c2]);
            s.x += v.x; s.y += v.y;
        }
        *(float2*)&g_S[(size_t)(b*Nx + i0 + i)*128 + c2*2] = s;
    }
}

// =======================================================================
// k_out: out = relu( g_P + S@M + g_c*vb )
// grid 128, block 256, 16 rows/block, M in smem, dyn smem 86016
// =======================================================================
#define KO_SMEM ((128*132) * 4 + (128*18) * 8)

__global__ void __launch_bounds__(256) k_out(float* __restrict__ out)
{
    extern __shared__ float sm[];
    float* Ms  = sm;                      // [128][132]
    u64*   St2 = (u64*)(sm + 128*132);    // [128][18] dup'd S
    const int t = threadIdx.x;
    const int row0 = blockIdx.x * 16;

#pragma unroll
    for (int n = 0; n < 16; n++) {
        int idx = t + n*256;
        int wk = idx >> 5, wn = (idx & 31) * 4;
        *(float4*)&Ms[wk*132 + wn] = *(const float4*)&g_M[wk*128 + wn];
    }
#pragma unroll
    for (int n = 0; n < 2; n++) {
        int idx = t + n*256;
        int r   = idx & 15;
        int kq  = (idx >> 4) * 4;
        float4 v = *(const float4*)&g_S[(size_t)(row0 + r)*128 + kq];
        St2[(kq+0)*18 + r] = dup2(v.x);
        St2[(kq+1)*18 + r] = dup2(v.y);
        St2[(kq+2)*18 + r] = dup2(v.z);
        St2[(kq+3)*18 + r] = dup2(v.w);
    }
    __syncthreads();

    const int ry = t >> 5, cx = t & 31;   // rows ry*2.., cols cx*4..
    u64 a00 = 0ull, a01 = 0ull, a10 = 0ull, a11 = 0ull;
#pragma unroll 4
    for (int k = 0; k < 128; k++) {
        ulonglong2 av = *(const ulonglong2*)&St2[k*18 + ry*2];   // broadcast
        ulonglong2 wv = *(const ulonglong2*)&Ms[k*132 + cx*4];
        fma2a(a00, av.x, wv.x); fma2a(a01, av.x, wv.y);
        fma2a(a10, av.y, wv.x); fma2a(a11, av.y, wv.y);
    }

    float4 vb4 = *(const float4*)&g_vb[cx*4];
#pragma unroll
    for (int r = 0; r < 2; r++) {
        int row = row0 + ry*2 + r;
        float cr = g_c[row];
        float4 pv = *(const float4*)&g_P[(size_t)row*128 + cx*4];
        float2 p = unpk(r ? a10 : a00), qv = unpk(r ? a11 : a01);
        float4 o;
        o.x = fmaxf(pv.x + fmaf(cr, vb4.x, p.x),  0.f);
        o.y = fmaxf(pv.y + fmaf(cr, vb4.y, p.y),  0.f);
        o.z = fmaxf(pv.z + fmaf(cr, vb4.z, qv.x), 0.f);
        o.w = fmaxf(pv.w + fmaf(cr, vb4.w, qv.y), 0.f);
        *(float4*)&out[(size_t)row*128 + cx*4] = o;
    }
}

// =======================================================================
extern "C" void kernel_launch(void* const* d_in, const int* in_sizes, int n_in,
                              void* d_out, int out_size)
{
    const float* h    = (const float*)d_in[0];
    const int*   adj  = (const int*)  d_in[1];
    const float* dist = (const float*)d_in[2];
    const float* Wm1  = (const float*)d_in[3];
    const float* bm1  = (const float*)d_in[4];
    const float* Wm2  = (const float*)d_in[5];
    const float* bm2  = (const float*)d_in[6];
    const float* Wa   = (const float*)d_in[7];
    const float* ba   = (const float*)d_in[8];
    const float* Wu   = (const float*)d_in[9];
    const float* bu   = (const float*)d_in[10];
    float* out = (float*)d_out;

    cudaFuncSetAttribute(k_stage1, cudaFuncAttributeMaxDynamicSharedMemorySize,
                         S1_SMEM);
    cudaFuncSetAttribute(k_pair, cudaFuncAttributeMaxDynamicSharedMemorySize,
                         PAIR_SMEM);
    cudaFuncSetAttribute(k_out, cudaFuncAttributeMaxDynamicSharedMemorySize,
                         KO_SMEM);

    k_stage1<<<205, 256, S1_SMEM>>>(h, Wm1, Wa, Wm2, bm2, Wu, bu);
    k_pair  <<<dim3(16, 8), 1024, PAIR_SMEM>>>(dist, adj, Wm1, bm1, Wa, ba);
    k_out   <<<128, 256, KO_SMEM>>>(out);
}